// round 8
// baseline (speedup 1.0000x reference)
#include <cuda_runtime.h>
#include <cuda_bf16.h>
#include <math.h>
#include <stdint.h>

#define T_STEPS 64
#define B_SZ    64
#define H_SZ    256
#define G_SZ    1024
#define M_TOT   4096      // T*B
#define V_SZ    32000

// ---------------- scratch ----------------------------------------------------
__device__ __align__(256) float g_bufA[M_TOT * H_SZ];
__device__ __align__(256) float g_bufB[M_TOT * H_SZ];
__device__ __align__(256) float g_gx[M_TOT * G_SZ];
__device__ __align__(256) float g_hinit[B_SZ * H_SZ];
__device__ __align__(256) float g_hfin[3 * B_SZ * H_SZ];
__device__ __align__(256) float g_cfin[3 * B_SZ * H_SZ];

// ---------------- distributed-flag grid barrier -------------------------------
__device__ volatile unsigned g_arrive[128];
__device__ volatile unsigned g_release;

// ================= bf16 2-split helpers ======================================
__device__ __forceinline__ uint32_t pack_bf2(unsigned short lo, unsigned short hi) {
    return ((uint32_t)hi << 16) | (uint32_t)lo;
}
__device__ __forceinline__ void split_bf(float a, unsigned short& h, unsigned short& l) {
    __nv_bfloat16 hb = __float2bfloat16_rn(a);
    float hf = __bfloat162float(hb);
    __nv_bfloat16 lb = __float2bfloat16_rn(a - hf);
    h = __bfloat16_as_ushort(hb);
    l = __bfloat16_as_ushort(lb);
}
__device__ __forceinline__ void split_store4(unsigned short* dhi, unsigned short* dlo, float4 a) {
    unsigned short h0, h1, h2, h3, l0, l1, l2, l3;
    split_bf(a.x, h0, l0); split_bf(a.y, h1, l1);
    split_bf(a.z, h2, l2); split_bf(a.w, h3, l3);
    uint2 hv; hv.x = pack_bf2(h0, h1); hv.y = pack_bf2(h2, h3);
    uint2 lv; lv.x = pack_bf2(l0, l1); lv.y = pack_bf2(l2, l3);
    *(uint2*)dhi = hv;
    *(uint2*)dlo = lv;
}

#define MMA_BF16(c, a, b) \
    asm volatile("mma.sync.aligned.m16n8k16.row.col.f32.bf16.bf16.f32 " \
        "{%0,%1,%2,%3}, {%4,%5,%6,%7}, {%8,%9}, {%0,%1,%2,%3};" \
        : "+f"((c)[0]), "+f"((c)[1]), "+f"((c)[2]), "+f"((c)[3]) \
        : "r"((a)[0]), "r"((a)[1]), "r"((a)[2]), "r"((a)[3]), \
          "r"((b)[0]), "r"((b)[1]))

// ================= bf16 2-split mma.sync GEMM ================================
#define BG_LD   264
#define BG_AHI  0
#define BG_ALO  (128 * BG_LD)
#define BG_BHI  (2 * 128 * BG_LD)
#define BG_BLO  (2 * 128 * BG_LD + 64 * BG_LD)
#define BG_SMEM ((2 * 128 * BG_LD + 2 * 64 * BG_LD) * 2)

__global__ void __launch_bounds__(256, 1) bgemm(
    const float* __restrict__ A, const float* __restrict__ W,
    const float* __restrict__ b1, const float* __restrict__ b2,
    float* __restrict__ C, int Ntot)
{
    extern __shared__ __align__(16) unsigned short bsm[];

    int tid = threadIdx.x;
    int wid = tid >> 5, lane = tid & 31;
    int g = lane >> 2, t = lane & 3;
    int warpM = wid >> 1, warpN = wid & 1;

    int nN = Ntot >> 6;
    int NT = nN << 5;
    int per = (NT + gridDim.x - 1) / gridDim.x;
    int tau0 = blockIdx.x * per;
    int tau1 = tau0 + per; if (tau1 > NT) tau1 = NT;
    int mPrev = -1;

    for (int tau = tau0; tau < tau1; tau++) {
        int mT = tau / nN, nT = tau - mT * nN;
        int m0 = mT << 7, n0 = nT << 6;

        __syncthreads();
        if (mT != mPrev) {
            const float* Ap = A + (size_t)m0 * 256;
#pragma unroll
            for (int v = 0; v < 32; v++) {
                int id = tid + 256 * v;
                int r = id >> 6, c4 = (id & 63) * 4;
                float4 a = __ldg((const float4*)(Ap + (size_t)r * 256 + c4));
                int hidx = r * BG_LD + c4;
                split_store4(bsm + BG_AHI + hidx, bsm + BG_ALO + hidx, a);
            }
            mPrev = mT;
        }
        {
            const float* Wp = W + (size_t)n0 * 256;
#pragma unroll
            for (int v = 0; v < 16; v++) {
                int id = tid + 256 * v;
                int r = id >> 6, c4 = (id & 63) * 4;
                float4 a = __ldg((const float4*)(Wp + (size_t)r * 256 + c4));
                int hidx = r * BG_LD + c4;
                split_store4(bsm + BG_BHI + hidx, bsm + BG_BLO + hidx, a);
            }
        }
        __syncthreads();

        float acc[2][4][4];
#pragma unroll
        for (int i = 0; i < 2; i++)
#pragma unroll
            for (int j = 0; j < 4; j++)
#pragma unroll
                for (int k = 0; k < 4; k++) acc[i][j][k] = 0.f;

        int aRow = warpM * 32;
        int bRow = warpN * 32;

#pragma unroll 4
        for (int kk = 0; kk < 256; kk += 16) {
            uint32_t ah[2][4], al[2][4];
#pragma unroll
            for (int ms = 0; ms < 2; ms++) {
                int r0 = aRow + ms * 16 + g;
                int i00 = r0 * BG_LD + 2 * t + kk;
                int i10 = (r0 + 8) * BG_LD + 2 * t + kk;
                ah[ms][0] = *(const uint32_t*)(bsm + BG_AHI + i00);
                ah[ms][1] = *(const uint32_t*)(bsm + BG_AHI + i10);
                ah[ms][2] = *(const uint32_t*)(bsm + BG_AHI + i00 + 8);
                ah[ms][3] = *(const uint32_t*)(bsm + BG_AHI + i10 + 8);
                al[ms][0] = *(const uint32_t*)(bsm + BG_ALO + i00);
                al[ms][1] = *(const uint32_t*)(bsm + BG_ALO + i10);
                al[ms][2] = *(const uint32_t*)(bsm + BG_ALO + i00 + 8);
                al[ms][3] = *(const uint32_t*)(bsm + BG_ALO + i10 + 8);
            }
            uint32_t bh[4][2], bl[4][2];
#pragma unroll
            for (int ns = 0; ns < 4; ns++) {
                int rw = bRow + ns * 8 + g;
                int ib = rw * BG_LD + 2 * t + kk;
                bh[ns][0] = *(const uint32_t*)(bsm + BG_BHI + ib);
                bh[ns][1] = *(const uint32_t*)(bsm + BG_BHI + ib + 8);
                bl[ns][0] = *(const uint32_t*)(bsm + BG_BLO + ib);
                bl[ns][1] = *(const uint32_t*)(bsm + BG_BLO + ib + 8);
            }
#pragma unroll
            for (int ms = 0; ms < 2; ms++)
#pragma unroll
                for (int ns = 0; ns < 4; ns++) {
                    MMA_BF16(acc[ms][ns], ah[ms], bh[ns]);
                    MMA_BF16(acc[ms][ns], ah[ms], bl[ns]);
                    MMA_BF16(acc[ms][ns], al[ms], bh[ns]);
                }
        }

#pragma unroll
        for (int ms = 0; ms < 2; ms++) {
            int row0 = m0 + aRow + ms * 16 + g;
#pragma unroll
            for (int ns = 0; ns < 4; ns++) {
                int col = n0 + bRow + ns * 8 + 2 * t;
                float bv0 = __ldg(b1 + col), bv1 = __ldg(b1 + col + 1);
                if (b2) { bv0 += __ldg(b2 + col); bv1 += __ldg(b2 + col + 1); }
                float2 o0, o1;
                o0.x = acc[ms][ns][0] + bv0; o0.y = acc[ms][ns][1] + bv1;
                o1.x = acc[ms][ns][2] + bv0; o1.y = acc[ms][ns][3] + bv1;
                *(float2*)(C + (size_t)row0 * Ntot + col) = o0;
                *(float2*)(C + (size_t)(row0 + 8) * Ntot + col) = o1;
            }
        }
    }
}

// ---------------- embedding --------------------------------------------------
__global__ void embed_k(const int* __restrict__ tok,
                        const float* __restrict__ emb,
                        float* __restrict__ out, int dec)
{
    int row = blockIdx.x;
    int tid = threadIdx.x;
    int t;
    if (dec) t = (row < B_SZ) ? 0 : tok[row - B_SZ];
    else     t = tok[row];
    out[row * H_SZ + tid] = emb[(size_t)t * H_SZ + tid];
}

// ---------------- h-init -----------------------------------------------------
__global__ void inith_k(const float* __restrict__ src, float* __restrict__ dst, int bcast)
{
    int b = blockIdx.x, k = threadIdx.x;
    dst[b * H_SZ + k] = bcast ? src[k] : src[b * H_SZ + k];
}

// ---------------- persistent recurrence --------------------------------------
#define REC_SMEM_BYTES ((64 * 260 + 8 * 256 + 4 * 64 * 2) * 4)

__device__ __forceinline__ float sigf(float x)   { return __fdividef(1.f, 1.f + __expf(-x)); }
__device__ __forceinline__ float tanh_f(float x) { float e = __expf(2.f * x); return __fdividef(e - 1.f, e + 1.f); }

__global__ void __launch_bounds__(256) rec_k(
    const float* __restrict__ Gx, const float* __restrict__ Whh,
    const float* __restrict__ hinit, const float* __restrict__ cinit, int cbcast,
    float* __restrict__ Xout, float* __restrict__ hfin, float* __restrict__ cfin)
{
    extern __shared__ float sm[];
    float* hs  = sm;                 // [64][260]
    float* Wsl = sm + 64 * 260;      // [8][256]
    float* gb  = Wsl + 8 * 256;      // [4][64][2]
    __shared__ unsigned s_base;

    int tid = threadIdx.x, bx = blockIdx.x;
    int b = tid & 63, q = tid >> 6;
    int wid = tid >> 5, lane = tid & 31;

    if (tid == 0) s_base = g_release;   // stable: prior launches quiesced

    // load Whh slice: rows q*256 + 2*bx + p -> local row 2q+p
#pragma unroll
    for (int v = 0; v < 2; v++) {
        int id = tid + 256 * v;
        int lr = id >> 6, k4 = id & 63;
        int qq = lr >> 1, p = lr & 1;
        int grow = qq * 256 + 2 * bx + p;
        float4 w = *(const float4*)(Whh + (size_t)grow * 256 + 4 * k4);
        *(float4*)&Wsl[lr * 256 + 4 * k4] = w;
    }

    float creg = 0.f, hlast = 0.f;
    int p_ = tid >> 6;
    int colp = 2 * bx + (p_ & 1);
    if (tid < 128)
        creg = cbcast ? cinit[colp] : cinit[b * H_SZ + colp];
    __syncthreads();
    unsigned base = s_base;

    for (int t = 0; t < T_STEPS; t++) {
        const float* hsrc = (t == 0) ? hinit : (Xout + (size_t)(t - 1) * B_SZ * H_SZ);
        // gate preload (overlaps with staging)
        float gx0 = __ldg(Gx + (size_t)(t * 64 + b) * 1024 + q * 256 + 2 * bx);
        float gx1 = __ldg(Gx + (size_t)(t * 64 + b) * 1024 + q * 256 + 2 * bx + 1);
        // stage h [64][256] -> smem [b][260]
#pragma unroll
        for (int v = 0; v < 16; v++) {
            int id = tid + 256 * v;
            int bb = id >> 6, k4 = id & 63;
            float4 hv = __ldcg((const float4*)(hsrc + bb * 256 + 4 * k4));
            *(float4*)&hs[bb * 260 + 4 * k4] = hv;
        }
        __syncthreads();

        const float* hrow = hs + b * 260;
        const float* w0 = Wsl + (2 * q) * 256;
        const float* w1 = w0 + 256;
        float s00 = 0.f, s01 = 0.f, s10 = 0.f, s11 = 0.f;   // 2 chains per row
#pragma unroll 8
        for (int k4 = 0; k4 < 64; k4++) {
            float4 hv = *(const float4*)(hrow + 4 * k4);
            float4 a  = *(const float4*)(w0 + 4 * k4);
            float4 c2 = *(const float4*)(w1 + 4 * k4);
            s00 += hv.x * a.x;  s01 += hv.y * a.y;
            s00 += hv.z * a.z;  s01 += hv.w * a.w;
            s10 += hv.x * c2.x; s11 += hv.y * c2.y;
            s10 += hv.z * c2.z; s11 += hv.w * c2.w;
        }
        gb[q * 128 + b * 2 + 0] = gx0 + s00 + s01;
        gb[q * 128 + b * 2 + 1] = gx1 + s10 + s11;
        __syncthreads();

        if (tid < 128) {
            int p = tid >> 6;
            float iv = gb[0 * 128 + b * 2 + p];
            float fv = gb[1 * 128 + b * 2 + p];
            float gv = gb[2 * 128 + b * 2 + p];
            float ov = gb[3 * 128 + b * 2 + p];
            float cn = sigf(fv) * creg + sigf(iv) * tanh_f(gv);
            float hn = sigf(ov) * tanh_f(cn);
            creg = cn; hlast = hn;
            Xout[(size_t)(t * 64 + b) * 256 + 2 * bx + p] = hn;
        }

        // ---- distributed-flag grid barrier ----
        unsigned tgt = base + (unsigned)t + 1u;
        __syncthreads();
        __threadfence();
        if (tid == 0) g_arrive[bx] = tgt;              // parallel arrivals
        if (bx == 0 && wid == 0) {                      // CTA0 warp0 polls
            for (;;) {
                bool mine = ((int)(g_arrive[lane]       - tgt) >= 0)
                         && ((int)(g_arrive[lane + 32]  - tgt) >= 0)
                         && ((int)(g_arrive[lane + 64]  - tgt) >= 0)
                         && ((int)(g_arrive[lane + 96]  - tgt) >= 0);
                if (__all_sync(0xffffffffu, mine)) break;
                __nanosleep(32);
            }
            if (lane == 0) g_release = tgt;
        }
        if (tid == 0) {
            while ((int)(g_release - tgt) < 0) { __nanosleep(32); }
        }
        __syncthreads();
        __threadfence();
    }

    if (tid < 128) {
        int p = tid >> 6;
        cfin[b * H_SZ + 2 * bx + p] = creg;
        hfin[b * H_SZ + 2 * bx + p] = hlast;
    }
}

// ---------------- row argmax over V ------------------------------------------
__global__ void argmax_k(const float* __restrict__ logits, float* __restrict__ outIdx)
{
    int m = blockIdx.x;
    const float* row = logits + (size_t)m * V_SZ;
    int tid = threadIdx.x;
    float bv = -__int_as_float(0x7f800000);
    int bi = 0;
    for (int n = tid; n < V_SZ; n += 256) {
        float v = row[n];
        if (v > bv) { bv = v; bi = n; }
    }
    __shared__ float sv[256];
    __shared__ int   si[256];
    sv[tid] = bv; si[tid] = bi;
    __syncthreads();
    for (int s = 128; s > 0; s >>= 1) {
        if (tid < s) {
            float ov = sv[tid + s]; int oi = si[tid + s];
            if (ov > sv[tid] || (ov == sv[tid] && oi < si[tid])) { sv[tid] = ov; si[tid] = oi; }
        }
        __syncthreads();
    }
    if (tid == 0) outIdx[m] = (float)si[0];
}

// ---------------- launch ------------------------------------------------------
extern "C" void kernel_launch(void* const* d_in, const int* in_sizes, int n_in,
                              void* d_out, int out_size)
{
    const int* inputs  = (const int*)d_in[0];
    const int* targets = (const int*)d_in[1];
    const float* enc_emb = (const float*)d_in[2];
    const float* enc_Wih = (const float*)d_in[3];
    const float* enc_Whh = (const float*)d_in[4];
    const float* enc_bih = (const float*)d_in[5];
    const float* enc_bhh = (const float*)d_in[6];
    const float* hidden0 = (const float*)d_in[7];
    const float* cell0   = (const float*)d_in[8];
    const float* dec_emb = (const float*)d_in[9];
    const float* dec_Wih = (const float*)d_in[10];
    const float* dec_Whh = (const float*)d_in[11];
    const float* dec_bih = (const float*)d_in[12];
    const float* dec_bhh = (const float*)d_in[13];
    const float* fc_W    = (const float*)d_in[14];
    const float* fc_b    = (const float*)d_in[15];
    float* out = (float*)d_out;

    float *bufA, *bufB, *gx, *hin, *hfin, *cfin;
    cudaGetSymbolAddress((void**)&bufA, g_bufA);
    cudaGetSymbolAddress((void**)&bufB, g_bufB);
    cudaGetSymbolAddress((void**)&gx,   g_gx);
    cudaGetSymbolAddress((void**)&hin,  g_hinit);
    cudaGetSymbolAddress((void**)&hfin, g_hfin);
    cudaGetSymbolAddress((void**)&cfin, g_cfin);

    cudaFuncSetAttribute(rec_k, cudaFuncAttributeMaxDynamicSharedMemorySize, REC_SMEM_BYTES);
    cudaFuncSetAttribute(bgemm, cudaFuncAttributeMaxDynamicSharedMemorySize, BG_SMEM);

    float* cur = bufA;
    float* nxt = bufB;

    // ---- encoder ----
    embed_k<<<M_TOT, 256>>>(inputs, enc_emb, cur, 0);
    for (int l = 0; l < 3; l++) {
        bgemm<<<148, 256, BG_SMEM>>>(cur, enc_Wih + (size_t)l * G_SZ * H_SZ,
                                     enc_bih + l * G_SZ, enc_bhh + l * G_SZ,
                                     gx, G_SZ);
        inith_k<<<B_SZ, 256>>>(hidden0 + l * H_SZ, hin, 1);
        rec_k<<<128, 256, REC_SMEM_BYTES>>>(gx, enc_Whh + (size_t)l * G_SZ * H_SZ,
                                            hin, cell0 + l * H_SZ, 1,
                                            nxt, hfin + (size_t)l * B_SZ * H_SZ,
                                            cfin + (size_t)l * B_SZ * H_SZ);
        float* tmp = cur; cur = nxt; nxt = tmp;
    }

    // ---- decoder (teacher forcing, shifted targets) ----
    embed_k<<<M_TOT, 256>>>(targets, dec_emb, cur, 1);
    for (int l = 0; l < 3; l++) {
        bgemm<<<148, 256, BG_SMEM>>>(cur, dec_Wih + (size_t)l * G_SZ * H_SZ,
                                     dec_bih + l * G_SZ, dec_bhh + l * G_SZ,
                                     gx, G_SZ);
        inith_k<<<B_SZ, 256>>>(hfin + (size_t)l * B_SZ * H_SZ, hin, 0);
        rec_k<<<128, 256, REC_SMEM_BYTES>>>(gx, dec_Whh + (size_t)l * G_SZ * H_SZ,
                                            hin, cfin + (size_t)l * B_SZ * H_SZ, 0,
                                            nxt, hfin + (size_t)l * B_SZ * H_SZ,
                                            cfin + (size_t)l * B_SZ * H_SZ);
        float* tmp = cur; cur = nxt; nxt = tmp;
    }

    // ---- FC projection to vocab (bf16 2-split mma.sync) ----
    bgemm<<<148, 256, BG_SMEM>>>(cur, fc_W, fc_b, (const float*)nullptr, out, V_SZ);

    // ---- predicted words ----
    long long need = (long long)M_TOT * V_SZ + M_TOT;
    if ((long long)out_size >= need)
        argmax_k<<<M_TOT, 256>>>(out, out + (size_t)M_TOT * V_SZ);
}

// round 9
// speedup vs baseline: 1.3493x; 1.3493x over previous
#include <cuda_runtime.h>
#include <cuda_bf16.h>
#include <math.h>
#include <stdint.h>

#define T_STEPS 64
#define B_SZ    64
#define H_SZ    256
#define G_SZ    1024
#define M_TOT   4096      // T*B
#define V_SZ    32000

// ---------------- scratch ----------------------------------------------------
__device__ __align__(256) float g_bufA[M_TOT * H_SZ];
__device__ __align__(256) float g_bufB[M_TOT * H_SZ];
__device__ __align__(256) float g_gx[M_TOT * G_SZ];
__device__ __align__(256) float g_hinit[B_SZ * H_SZ];
__device__ __align__(256) float g_hfin[3 * B_SZ * H_SZ];
__device__ __align__(256) float g_cfin[3 * B_SZ * H_SZ];
// bf16 hi/lo planes of current h (produced each step by owning CTAs)
__device__ __align__(256) unsigned short g_hbf_hi[B_SZ * H_SZ];
__device__ __align__(256) unsigned short g_hbf_lo[B_SZ * H_SZ];

// ---------------- two-level grid barrier --------------------------------------
__device__ unsigned g_cnt[8 * 32];        // group counters, 128B apart
__device__ unsigned g_root;
__device__ volatile unsigned g_bar_gen;

// ================= bf16 2-split helpers ======================================
__device__ __forceinline__ uint32_t pack_bf2(unsigned short lo, unsigned short hi) {
    return ((uint32_t)hi << 16) | (uint32_t)lo;
}
__device__ __forceinline__ void split_bf(float a, unsigned short& h, unsigned short& l) {
    __nv_bfloat16 hb = __float2bfloat16_rn(a);
    float hf = __bfloat162float(hb);
    __nv_bfloat16 lb = __float2bfloat16_rn(a - hf);
    h = __bfloat16_as_ushort(hb);
    l = __bfloat16_as_ushort(lb);
}
__device__ __forceinline__ void split_store4(unsigned short* dhi, unsigned short* dlo, float4 a) {
    unsigned short h0, h1, h2, h3, l0, l1, l2, l3;
    split_bf(a.x, h0, l0); split_bf(a.y, h1, l1);
    split_bf(a.z, h2, l2); split_bf(a.w, h3, l3);
    uint2 hv; hv.x = pack_bf2(h0, h1); hv.y = pack_bf2(h2, h3);
    uint2 lv; lv.x = pack_bf2(l0, l1); lv.y = pack_bf2(l2, l3);
    *(uint2*)dhi = hv;
    *(uint2*)dlo = lv;
}

#define MMA_BF16(c, a, b) \
    asm volatile("mma.sync.aligned.m16n8k16.row.col.f32.bf16.bf16.f32 " \
        "{%0,%1,%2,%3}, {%4,%5,%6,%7}, {%8,%9}, {%0,%1,%2,%3};" \
        : "+f"((c)[0]), "+f"((c)[1]), "+f"((c)[2]), "+f"((c)[3]) \
        : "r"((a)[0]), "r"((a)[1]), "r"((a)[2]), "r"((a)[3]), \
          "r"((b)[0]), "r"((b)[1]))

#define LDSM_X4(r, addr) \
    asm volatile("ldmatrix.sync.aligned.m8n8.x4.shared.b16 {%0,%1,%2,%3}, [%4];" \
        : "=r"((r)[0]), "=r"((r)[1]), "=r"((r)[2]), "=r"((r)[3]) : "r"(addr))

__device__ __forceinline__ uint32_t smem_u32(const void* p) {
    uint32_t a;
    asm("{ .reg .u64 t; cvta.to.shared.u64 t, %1; cvt.u32.u64 %0, t; }" : "=r"(a) : "l"(p));
    return a;
}

// ================= bf16 2-split mma.sync GEMM (unchanged from R6 pass) =======
#define BG_LD   264
#define BG_AHI  0
#define BG_ALO  (128 * BG_LD)
#define BG_BHI  (2 * 128 * BG_LD)
#define BG_BLO  (2 * 128 * BG_LD + 64 * BG_LD)
#define BG_SMEM ((2 * 128 * BG_LD + 2 * 64 * BG_LD) * 2)

__global__ void __launch_bounds__(256, 1) bgemm(
    const float* __restrict__ A, const float* __restrict__ W,
    const float* __restrict__ b1, const float* __restrict__ b2,
    float* __restrict__ C, int Ntot)
{
    extern __shared__ __align__(16) unsigned short bsm[];

    int tid = threadIdx.x;
    int wid = tid >> 5, lane = tid & 31;
    int g = lane >> 2, t = lane & 3;
    int warpM = wid >> 1, warpN = wid & 1;

    int nN = Ntot >> 6;
    int NT = nN << 5;
    int per = (NT + gridDim.x - 1) / gridDim.x;
    int tau0 = blockIdx.x * per;
    int tau1 = tau0 + per; if (tau1 > NT) tau1 = NT;
    int mPrev = -1;

    for (int tau = tau0; tau < tau1; tau++) {
        int mT = tau / nN, nT = tau - mT * nN;
        int m0 = mT << 7, n0 = nT << 6;

        __syncthreads();
        if (mT != mPrev) {
            const float* Ap = A + (size_t)m0 * 256;
#pragma unroll
            for (int v = 0; v < 32; v++) {
                int id = tid + 256 * v;
                int r = id >> 6, c4 = (id & 63) * 4;
                float4 a = __ldg((const float4*)(Ap + (size_t)r * 256 + c4));
                int hidx = r * BG_LD + c4;
                split_store4(bsm + BG_AHI + hidx, bsm + BG_ALO + hidx, a);
            }
            mPrev = mT;
        }
        {
            const float* Wp = W + (size_t)n0 * 256;
#pragma unroll
            for (int v = 0; v < 16; v++) {
                int id = tid + 256 * v;
                int r = id >> 6, c4 = (id & 63) * 4;
                float4 a = __ldg((const float4*)(Wp + (size_t)r * 256 + c4));
                int hidx = r * BG_LD + c4;
                split_store4(bsm + BG_BHI + hidx, bsm + BG_BLO + hidx, a);
            }
        }
        __syncthreads();

        float acc[2][4][4];
#pragma unroll
        for (int i = 0; i < 2; i++)
#pragma unroll
            for (int j = 0; j < 4; j++)
#pragma unroll
                for (int k = 0; k < 4; k++) acc[i][j][k] = 0.f;

        int aRow = warpM * 32;
        int bRow = warpN * 32;

#pragma unroll 4
        for (int kk = 0; kk < 256; kk += 16) {
            uint32_t ah[2][4], al[2][4];
#pragma unroll
            for (int ms = 0; ms < 2; ms++) {
                int r0 = aRow + ms * 16 + g;
                int i00 = r0 * BG_LD + 2 * t + kk;
                int i10 = (r0 + 8) * BG_LD + 2 * t + kk;
                ah[ms][0] = *(const uint32_t*)(bsm + BG_AHI + i00);
                ah[ms][1] = *(const uint32_t*)(bsm + BG_AHI + i10);
                ah[ms][2] = *(const uint32_t*)(bsm + BG_AHI + i00 + 8);
                ah[ms][3] = *(const uint32_t*)(bsm + BG_AHI + i10 + 8);
                al[ms][0] = *(const uint32_t*)(bsm + BG_ALO + i00);
                al[ms][1] = *(const uint32_t*)(bsm + BG_ALO + i10);
                al[ms][2] = *(const uint32_t*)(bsm + BG_ALO + i00 + 8);
                al[ms][3] = *(const uint32_t*)(bsm + BG_ALO + i10 + 8);
            }
            uint32_t bh[4][2], bl[4][2];
#pragma unroll
            for (int ns = 0; ns < 4; ns++) {
                int rw = bRow + ns * 8 + g;
                int ib = rw * BG_LD + 2 * t + kk;
                bh[ns][0] = *(const uint32_t*)(bsm + BG_BHI + ib);
                bh[ns][1] = *(const uint32_t*)(bsm + BG_BHI + ib + 8);
                bl[ns][0] = *(const uint32_t*)(bsm + BG_BLO + ib);
                bl[ns][1] = *(const uint32_t*)(bsm + BG_BLO + ib + 8);
            }
#pragma unroll
            for (int ms = 0; ms < 2; ms++)
#pragma unroll
                for (int ns = 0; ns < 4; ns++) {
                    MMA_BF16(acc[ms][ns], ah[ms], bh[ns]);
                    MMA_BF16(acc[ms][ns], ah[ms], bl[ns]);
                    MMA_BF16(acc[ms][ns], al[ms], bh[ns]);
                }
        }

#pragma unroll
        for (int ms = 0; ms < 2; ms++) {
            int row0 = m0 + aRow + ms * 16 + g;
#pragma unroll
            for (int ns = 0; ns < 4; ns++) {
                int col = n0 + bRow + ns * 8 + 2 * t;
                float bv0 = __ldg(b1 + col), bv1 = __ldg(b1 + col + 1);
                if (b2) { bv0 += __ldg(b2 + col); bv1 += __ldg(b2 + col + 1); }
                float2 o0, o1;
                o0.x = acc[ms][ns][0] + bv0; o0.y = acc[ms][ns][1] + bv1;
                o1.x = acc[ms][ns][2] + bv0; o1.y = acc[ms][ns][3] + bv1;
                *(float2*)(C + (size_t)row0 * Ntot + col) = o0;
                *(float2*)(C + (size_t)(row0 + 8) * Ntot + col) = o1;
            }
        }
    }
}

// ---------------- embedding --------------------------------------------------
__global__ void embed_k(const int* __restrict__ tok,
                        const float* __restrict__ emb,
                        float* __restrict__ out, int dec)
{
    int row = blockIdx.x;
    int tid = threadIdx.x;
    int t;
    if (dec) t = (row < B_SZ) ? 0 : tok[row - B_SZ];
    else     t = tok[row];
    out[row * H_SZ + tid] = emb[(size_t)t * H_SZ + tid];
}

// ---------------- h-init -----------------------------------------------------
__global__ void inith_k(const float* __restrict__ src, float* __restrict__ dst, int bcast)
{
    int b = blockIdx.x, k = threadIdx.x;
    dst[b * H_SZ + k] = bcast ? src[k] : src[b * H_SZ + k];
}

// ---------------- persistent recurrence (HMMA) --------------------------------
// 128 CTAs x 256 thr. CTA bx owns hidden cols {2bx, 2bx+1}; gate rows q*256+2bx+p.
// Per step: G[64,8] = h[64,256] @ Wsl[8,256]^T via mma.sync bf16 2-split.
// Whh B-fragments live in registers (split once at launch). h staged from
// bf16 hi/lo global planes written by the producer threads each step.
#define RC_LDH   264                                  // halves per smem row
#define RC_HS_HI 0
#define RC_HS_LO (64 * RC_LDH * 2)                    // 33792 B
#define RC_GBUF  (2 * 64 * RC_LDH * 2)                // 67584
#define RC_RED   (RC_GBUF + 64 * 10 * 4)              // 70144
#define REC_SMEM_BYTES (RC_RED + 64 * 10 * 4)         // 72704

__device__ __forceinline__ float sigf(float x)   { return __fdividef(1.f, 1.f + __expf(-x)); }
__device__ __forceinline__ float tanh_f(float x) { float e = __expf(2.f * x); return __fdividef(e - 1.f, e + 1.f); }

__global__ void __launch_bounds__(256, 1) rec_k(
    const float* __restrict__ Gx, const float* __restrict__ Whh,
    const float* __restrict__ hinit, const float* __restrict__ cinit, int cbcast,
    float* __restrict__ Xout, float* __restrict__ hfin, float* __restrict__ cfin)
{
    extern __shared__ __align__(16) char rsm[];
    unsigned short* hsHi = (unsigned short*)(rsm + RC_HS_HI);
    unsigned short* hsLo = (unsigned short*)(rsm + RC_HS_LO);
    float* gbuf = (float*)(rsm + RC_GBUF);   // [64][10]
    float* red  = (float*)(rsm + RC_RED);    // [64][10]
    __shared__ unsigned s_base;

    int tid = threadIdx.x, bx = blockIdx.x;
    int wid = tid >> 5, lane = tid & 31;
    int g = lane >> 2, t4 = lane & 3;
    int mtile = wid & 3, khalf = wid >> 2;
    int b = tid & 63, p = tid >> 6;          // activation mapping (tid<128)

    uint32_t hsHiA = smem_u32(hsHi);
    uint32_t hsLoA = smem_u32(hsLo);

    if (tid == 0) s_base = g_bar_gen;

    // ---- preload Whh B-fragments into registers (hi/lo) ----
    // n index (0..7) = lane's g: global gate row = (g>>1)*256 + 2*bx + (g&1)
    uint32_t bfh[8][2], bfl[8][2];
    {
        int grow = (g >> 1) * 256 + 2 * bx + (g & 1);
        const float* wr = Whh + (size_t)grow * 256 + khalf * 128;
#pragma unroll
        for (int kt = 0; kt < 8; kt++) {
            int k0 = kt * 16 + 2 * t4;
            float w0 = __ldg(wr + k0),     w1 = __ldg(wr + k0 + 1);
            float w2 = __ldg(wr + k0 + 8), w3 = __ldg(wr + k0 + 9);
            unsigned short h0, h1, h2, h3, l0, l1, l2, l3;
            split_bf(w0, h0, l0); split_bf(w1, h1, l1);
            split_bf(w2, h2, l2); split_bf(w3, h3, l3);
            bfh[kt][0] = pack_bf2(h0, h1); bfh[kt][1] = pack_bf2(h2, h3);
            bfl[kt][0] = pack_bf2(l0, l1); bfl[kt][1] = pack_bf2(l2, l3);
        }
    }

    // ---- init c (register) and publish h0 planes for owned cols ----
    float creg = 0.f, hlast = 0.f;
    int colp = 2 * bx + p;
    if (tid < 128) {
        creg = cbcast ? cinit[colp] : cinit[b * H_SZ + colp];
        float h0 = hinit[b * H_SZ + colp];
        unsigned short hh, hl;
        split_bf(h0, hh, hl);
        g_hbf_hi[b * 256 + colp] = hh;
        g_hbf_lo[b * 256 + colp] = hl;
        hlast = h0;
    }
    __syncthreads();
    unsigned base = s_base;

    // grid barrier helper (two-level atomic, generation-gated)
#define GRID_BAR(TGT) do { \
        __syncthreads(); \
        __threadfence(); \
        if (tid == 0) { \
            if (atomicAdd(&g_cnt[(bx >> 4) << 5], 1u) == 15u) { \
                if (atomicAdd(&g_root, 1u) == 7u) { \
                    g_root = 0u; \
                    _Pragma("unroll") \
                    for (int i_ = 0; i_ < 8; i_++) \
                        ((volatile unsigned*)g_cnt)[i_ << 5] = 0u; \
                    __threadfence(); \
                    g_bar_gen = (TGT); \
                } \
            } \
            while ((int)(g_bar_gen - (TGT)) < 0) { } \
        } \
        __syncthreads(); \
        __threadfence(); \
    } while (0)

    GRID_BAR(base + 1u);   // h0 planes visible everywhere

    const uint32_t ldRowB = RC_LDH * 2;   // 528 bytes per smem row
    for (int t = 0; t < T_STEPS; t++) {
        // ---- stage bf16 planes -> smem (coalesced float4) ----
#pragma unroll
        for (int v = 0; v < 8; v++) {
            int id = tid + 256 * v;       // 2048 float4 per plane
            int bb = id >> 5, k8 = id & 31;
            float4 hv = __ldcg((const float4*)g_hbf_hi + id);
            float4 lv = __ldcg((const float4*)g_hbf_lo + id);
            *(float4*)((char*)hsHi + bb * ldRowB + k8 * 16) = hv;
            *(float4*)((char*)hsLo + bb * ldRowB + k8 * 16) = lv;
        }
        __syncthreads();

        // ---- MMA: warp (mtile, khalf) computes partial G[16,8] over K half ----
        float c[4] = {0.f, 0.f, 0.f, 0.f};
        {
            uint32_t rowA = (uint32_t)(mtile * 16 + (lane & 15)) * ldRowB
                          + (uint32_t)(khalf * 128) * 2 + (uint32_t)(lane >> 4) * 16;
#pragma unroll
            for (int kt = 0; kt < 8; kt++) {
                uint32_t ahi[4], alo[4];
                LDSM_X4(ahi, hsHiA + rowA + kt * 32);
                LDSM_X4(alo, hsLoA + rowA + kt * 32);
                MMA_BF16(c, ahi, bfh[kt]);
                MMA_BF16(c, ahi, bfl[kt]);
                MMA_BF16(c, alo, bfh[kt]);
            }
        }

        // ---- reduce khalf partners, store G to gbuf ----
        if (khalf == 1) {
            int r0 = mtile * 16 + g;
            *(float2*)(red + r0 * 10 + 2 * t4)       = make_float2(c[0], c[1]);
            *(float2*)(red + (r0 + 8) * 10 + 2 * t4) = make_float2(c[2], c[3]);
        }
        __syncthreads();
        if (khalf == 0) {
            int r0 = mtile * 16 + g;
            float2 o0 = *(float2*)(red + r0 * 10 + 2 * t4);
            float2 o1 = *(float2*)(red + (r0 + 8) * 10 + 2 * t4);
            *(float2*)(gbuf + r0 * 10 + 2 * t4)       = make_float2(c[0] + o0.x, c[1] + o0.y);
            *(float2*)(gbuf + (r0 + 8) * 10 + 2 * t4) = make_float2(c[2] + o1.x, c[3] + o1.y);
        }
        __syncthreads();

        // ---- activation (tid<128: batch b, col p) ----
        if (tid < 128) {
            const float* gxr = Gx + (size_t)(t * 64 + b) * 1024 + 2 * bx + p;
            float iv = gbuf[b * 10 + 0 + p] + __ldg(gxr);
            float fv = gbuf[b * 10 + 2 + p] + __ldg(gxr + 256);
            float gv = gbuf[b * 10 + 4 + p] + __ldg(gxr + 512);
            float ov = gbuf[b * 10 + 6 + p] + __ldg(gxr + 768);
            float cn = sigf(fv) * creg + sigf(iv) * tanh_f(gv);
            float hn = sigf(ov) * tanh_f(cn);
            creg = cn; hlast = hn;
            Xout[(size_t)(t * 64 + b) * 256 + colp] = hn;
            unsigned short hh, hl;
            split_bf(hn, hh, hl);
            g_hbf_hi[b * 256 + colp] = hh;
            g_hbf_lo[b * 256 + colp] = hl;
        }

        GRID_BAR(base + 2u + (unsigned)t);
    }

    if (tid < 128) {
        cfin[b * H_SZ + colp] = creg;
        hfin[b * H_SZ + colp] = hlast;
    }
#undef GRID_BAR
}

// ---------------- row argmax over V ------------------------------------------
__global__ void argmax_k(const float* __restrict__ logits, float* __restrict__ outIdx)
{
    int m = blockIdx.x;
    const float* row = logits + (size_t)m * V_SZ;
    int tid = threadIdx.x;
    float bv = -__int_as_float(0x7f800000);
    int bi = 0;
    for (int n = tid; n < V_SZ; n += 256) {
        float v = row[n];
        if (v > bv) { bv = v; bi = n; }
    }
    __shared__ float sv[256];
    __shared__ int   si[256];
    sv[tid] = bv; si[tid] = bi;
    __syncthreads();
    for (int s = 128; s > 0; s >>= 1) {
        if (tid < s) {
            float ov = sv[tid + s]; int oi = si[tid + s];
            if (ov > sv[tid] || (ov == sv[tid] && oi < si[tid])) { sv[tid] = ov; si[tid] = oi; }
        }
        __syncthreads();
    }
    if (tid == 0) outIdx[m] = (float)si[0];
}

// ---------------- launch ------------------------------------------------------
extern "C" void kernel_launch(void* const* d_in, const int* in_sizes, int n_in,
                              void* d_out, int out_size)
{
    const int* inputs  = (const int*)d_in[0];
    const int* targets = (const int*)d_in[1];
    const float* enc_emb = (const float*)d_in[2];
    const float* enc_Wih = (const float*)d_in[3];
    const float* enc_Whh = (const float*)d_in[4];
    const float* enc_bih = (const float*)d_in[5];
    const float* enc_bhh = (const float*)d_in[6];
    const float* hidden0 = (const float*)d_in[7];
    const float* cell0   = (const float*)d_in[8];
    const float* dec_emb = (const float*)d_in[9];
    const float* dec_Wih = (const float*)d_in[10];
    const float* dec_Whh = (const float*)d_in[11];
    const float* dec_bih = (const float*)d_in[12];
    const float* dec_bhh = (const float*)d_in[13];
    const float* fc_W    = (const float*)d_in[14];
    const float* fc_b    = (const float*)d_in[15];
    float* out = (float*)d_out;

    float *bufA, *bufB, *gx, *hin, *hfin, *cfin;
    cudaGetSymbolAddress((void**)&bufA, g_bufA);
    cudaGetSymbolAddress((void**)&bufB, g_bufB);
    cudaGetSymbolAddress((void**)&gx,   g_gx);
    cudaGetSymbolAddress((void**)&hin,  g_hinit);
    cudaGetSymbolAddress((void**)&hfin, g_hfin);
    cudaGetSymbolAddress((void**)&cfin, g_cfin);

    cudaFuncSetAttribute(rec_k, cudaFuncAttributeMaxDynamicSharedMemorySize, REC_SMEM_BYTES);
    cudaFuncSetAttribute(bgemm, cudaFuncAttributeMaxDynamicSharedMemorySize, BG_SMEM);

    float* cur = bufA;
    float* nxt = bufB;

    // ---- encoder ----
    embed_k<<<M_TOT, 256>>>(inputs, enc_emb, cur, 0);
    for (int l = 0; l < 3; l++) {
        bgemm<<<148, 256, BG_SMEM>>>(cur, enc_Wih + (size_t)l * G_SZ * H_SZ,
                                     enc_bih + l * G_SZ, enc_bhh + l * G_SZ,
                                     gx, G_SZ);
        inith_k<<<B_SZ, 256>>>(hidden0 + l * H_SZ, hin, 1);
        rec_k<<<128, 256, REC_SMEM_BYTES>>>(gx, enc_Whh + (size_t)l * G_SZ * H_SZ,
                                            hin, cell0 + l * H_SZ, 1,
                                            nxt, hfin + (size_t)l * B_SZ * H_SZ,
                                            cfin + (size_t)l * B_SZ * H_SZ);
        float* tmp = cur; cur = nxt; nxt = tmp;
    }

    // ---- decoder (teacher forcing, shifted targets) ----
    embed_k<<<M_TOT, 256>>>(targets, dec_emb, cur, 1);
    for (int l = 0; l < 3; l++) {
        bgemm<<<148, 256, BG_SMEM>>>(cur, dec_Wih + (size_t)l * G_SZ * H_SZ,
                                     dec_bih + l * G_SZ, dec_bhh + l * G_SZ,
                                     gx, G_SZ);
        inith_k<<<B_SZ, 256>>>(hfin + (size_t)l * B_SZ * H_SZ, hin, 0);
        rec_k<<<128, 256, REC_SMEM_BYTES>>>(gx, dec_Whh + (size_t)l * G_SZ * H_SZ,
                                            hin, cfin + (size_t)l * B_SZ * H_SZ, 0,
                                            nxt, hfin + (size_t)l * B_SZ * H_SZ,
                                            cfin + (size_t)l * B_SZ * H_SZ);
        float* tmp = cur; cur = nxt; nxt = tmp;
    }

    // ---- FC projection to vocab (bf16 2-split mma.sync) ----
    bgemm<<<148, 256, BG_SMEM>>>(cur, fc_W, fc_b, (const float*)nullptr, out, V_SZ);

    // ---- predicted words ----
    long long need = (long long)M_TOT * V_SZ + M_TOT;
    if ((long long)out_size >= need)
        argmax_k<<<M_TOT, 256>>>(out, out + (size_t)M_TOT * V_SZ);
}

// round 10
// speedup vs baseline: 1.3866x; 1.0277x over previous
#include <cuda_runtime.h>
#include <cuda_bf16.h>
#include <math.h>
#include <stdint.h>

#define T_STEPS 64
#define B_SZ    64
#define H_SZ    256
#define G_SZ    1024
#define M_TOT   4096      // T*B
#define V_SZ    32000

// ---------------- scratch ----------------------------------------------------
__device__ __align__(256) float g_bufA[M_TOT * H_SZ];
__device__ __align__(256) float g_bufB[M_TOT * H_SZ];
__device__ __align__(256) float g_gx[M_TOT * G_SZ];
__device__ __align__(256) float g_hfin[3 * B_SZ * H_SZ];
__device__ __align__(256) float g_cfin[3 * B_SZ * H_SZ];

// ================= bf16 2-split helpers ======================================
__device__ __forceinline__ uint32_t pack_bf2(unsigned short lo, unsigned short hi) {
    return ((uint32_t)hi << 16) | (uint32_t)lo;
}
__device__ __forceinline__ void split_bf(float a, unsigned short& h, unsigned short& l) {
    __nv_bfloat16 hb = __float2bfloat16_rn(a);
    float hf = __bfloat162float(hb);
    __nv_bfloat16 lb = __float2bfloat16_rn(a - hf);
    h = __bfloat16_as_ushort(hb);
    l = __bfloat16_as_ushort(lb);
}
__device__ __forceinline__ void split_store4(unsigned short* dhi, unsigned short* dlo, float4 a) {
    unsigned short h0, h1, h2, h3, l0, l1, l2, l3;
    split_bf(a.x, h0, l0); split_bf(a.y, h1, l1);
    split_bf(a.z, h2, l2); split_bf(a.w, h3, l3);
    uint2 hv; hv.x = pack_bf2(h0, h1); hv.y = pack_bf2(h2, h3);
    uint2 lv; lv.x = pack_bf2(l0, l1); lv.y = pack_bf2(l2, l3);
    *(uint2*)dhi = hv;
    *(uint2*)dlo = lv;
}

#define MMA_BF16(c, a, b) \
    asm volatile("mma.sync.aligned.m16n8k16.row.col.f32.bf16.bf16.f32 " \
        "{%0,%1,%2,%3}, {%4,%5,%6,%7}, {%8,%9}, {%0,%1,%2,%3};" \
        : "+f"((c)[0]), "+f"((c)[1]), "+f"((c)[2]), "+f"((c)[3]) \
        : "r"((a)[0]), "r"((a)[1]), "r"((a)[2]), "r"((a)[3]), \
          "r"((b)[0]), "r"((b)[1]))

__device__ __forceinline__ uint32_t smem_u32(const void* p) {
    uint32_t a;
    asm("{ .reg .u64 t; cvta.to.shared.u64 t, %1; cvt.u32.u64 %0, t; }" : "=r"(a) : "l"(p));
    return a;
}

// ================= bf16 2-split mma.sync GEMM (proven R6/R9) =================
#define BG_LD   264
#define BG_AHI  0
#define BG_ALO  (128 * BG_LD)
#define BG_BHI  (2 * 128 * BG_LD)
#define BG_BLO  (2 * 128 * BG_LD + 64 * BG_LD)
#define BG_SMEM ((2 * 128 * BG_LD + 2 * 64 * BG_LD) * 2)

__global__ void __launch_bounds__(256, 1) bgemm(
    const float* __restrict__ A, const float* __restrict__ W,
    const float* __restrict__ b1, const float* __restrict__ b2,
    float* __restrict__ C, int Ntot)
{
    extern __shared__ __align__(16) unsigned short bsm[];

    int tid = threadIdx.x;
    int wid = tid >> 5, lane = tid & 31;
    int g = lane >> 2, t = lane & 3;
    int warpM = wid >> 1, warpN = wid & 1;

    int nN = Ntot >> 6;
    int NT = nN << 5;
    int per = (NT + gridDim.x - 1) / gridDim.x;
    int tau0 = blockIdx.x * per;
    int tau1 = tau0 + per; if (tau1 > NT) tau1 = NT;
    int mPrev = -1;

    for (int tau = tau0; tau < tau1; tau++) {
        int mT = tau / nN, nT = tau - mT * nN;
        int m0 = mT << 7, n0 = nT << 6;

        __syncthreads();
        if (mT != mPrev) {
            const float* Ap = A + (size_t)m0 * 256;
#pragma unroll
            for (int v = 0; v < 32; v++) {
                int id = tid + 256 * v;
                int r = id >> 6, c4 = (id & 63) * 4;
                float4 a = __ldg((const float4*)(Ap + (size_t)r * 256 + c4));
                int hidx = r * BG_LD + c4;
                split_store4(bsm + BG_AHI + hidx, bsm + BG_ALO + hidx, a);
            }
            mPrev = mT;
        }
        {
            const float* Wp = W + (size_t)n0 * 256;
#pragma unroll
            for (int v = 0; v < 16; v++) {
                int id = tid + 256 * v;
                int r = id >> 6, c4 = (id & 63) * 4;
                float4 a = __ldg((const float4*)(Wp + (size_t)r * 256 + c4));
                int hidx = r * BG_LD + c4;
                split_store4(bsm + BG_BHI + hidx, bsm + BG_BLO + hidx, a);
            }
        }
        __syncthreads();

        float acc[2][4][4];
#pragma unroll
        for (int i = 0; i < 2; i++)
#pragma unroll
            for (int j = 0; j < 4; j++)
#pragma unroll
                for (int k = 0; k < 4; k++) acc[i][j][k] = 0.f;

        int aRow = warpM * 32;
        int bRow = warpN * 32;

#pragma unroll 4
        for (int kk = 0; kk < 256; kk += 16) {
            uint32_t ah[2][4], al[2][4];
#pragma unroll
            for (int ms = 0; ms < 2; ms++) {
                int r0 = aRow + ms * 16 + g;
                int i00 = r0 * BG_LD + 2 * t + kk;
                int i10 = (r0 + 8) * BG_LD + 2 * t + kk;
                ah[ms][0] = *(const uint32_t*)(bsm + BG_AHI + i00);
                ah[ms][1] = *(const uint32_t*)(bsm + BG_AHI + i10);
                ah[ms][2] = *(const uint32_t*)(bsm + BG_AHI + i00 + 8);
                ah[ms][3] = *(const uint32_t*)(bsm + BG_AHI + i10 + 8);
                al[ms][0] = *(const uint32_t*)(bsm + BG_ALO + i00);
                al[ms][1] = *(const uint32_t*)(bsm + BG_ALO + i10);
                al[ms][2] = *(const uint32_t*)(bsm + BG_ALO + i00 + 8);
                al[ms][3] = *(const uint32_t*)(bsm + BG_ALO + i10 + 8);
            }
            uint32_t bh[4][2], bl[4][2];
#pragma unroll
            for (int ns = 0; ns < 4; ns++) {
                int rw = bRow + ns * 8 + g;
                int ib = rw * BG_LD + 2 * t + kk;
                bh[ns][0] = *(const uint32_t*)(bsm + BG_BHI + ib);
                bh[ns][1] = *(const uint32_t*)(bsm + BG_BHI + ib + 8);
                bl[ns][0] = *(const uint32_t*)(bsm + BG_BLO + ib);
                bl[ns][1] = *(const uint32_t*)(bsm + BG_BLO + ib + 8);
            }
#pragma unroll
            for (int ms = 0; ms < 2; ms++)
#pragma unroll
                for (int ns = 0; ns < 4; ns++) {
                    MMA_BF16(acc[ms][ns], ah[ms], bh[ns]);
                    MMA_BF16(acc[ms][ns], ah[ms], bl[ns]);
                    MMA_BF16(acc[ms][ns], al[ms], bh[ns]);
                }
        }

#pragma unroll
        for (int ms = 0; ms < 2; ms++) {
            int row0 = m0 + aRow + ms * 16 + g;
#pragma unroll
            for (int ns = 0; ns < 4; ns++) {
                int col = n0 + bRow + ns * 8 + 2 * t;
                float bv0 = __ldg(b1 + col), bv1 = __ldg(b1 + col + 1);
                if (b2) { bv0 += __ldg(b2 + col); bv1 += __ldg(b2 + col + 1); }
                float2 o0, o1;
                o0.x = acc[ms][ns][0] + bv0; o0.y = acc[ms][ns][1] + bv1;
                o1.x = acc[ms][ns][2] + bv0; o1.y = acc[ms][ns][3] + bv1;
                *(float2*)(C + (size_t)row0 * Ntot + col) = o0;
                *(float2*)(C + (size_t)(row0 + 8) * Ntot + col) = o1;
            }
        }
    }
}

// ---------------- embedding --------------------------------------------------
__global__ void embed_k(const int* __restrict__ tok,
                        const float* __restrict__ emb,
                        float* __restrict__ out, int dec)
{
    int row = blockIdx.x;
    int tid = threadIdx.x;
    int t;
    if (dec) t = (row < B_SZ) ? 0 : tok[row - B_SZ];
    else     t = tok[row];
    out[row * H_SZ + tid] = emb[(size_t)t * H_SZ + tid];
}

// ---------------- clustered recurrence ----------------------------------------
// 16 clusters x 8 CTAs. Cluster cl owns batches [4cl, 4cl+4); CTA rank r owns
// hidden cols [32r, 32r+32) (gate rows q*256+32r+[0,32), all 4 gates -> local
// activation). Per step: gates[4b,128rows] = h[4,256] @ Wsl^T (fp32 FFMA, W in
// smem), activation, h chunk pushed to 7 peers via DSMEM, one cluster barrier.
// Clusters fully independent -> no grid sync, deadlock-free.
#define RW       260                      // W row stride (floats), conflict-free
#define SM_W     0
#define SM_H0    (128 * RW)               // 33280
#define SM_H1    (SM_H0 + 4 * RW)         // 34320
#define SM_RED   (SM_H1 + 4 * RW)         // 35360
#define SM_GB    (SM_RED + 512)           // 35872
#define REC_SMEM_BYTES ((SM_GB + 512) * 4)   // 145536

__device__ __forceinline__ float sigf(float x)   { return __fdividef(1.f, 1.f + __expf(-x)); }
__device__ __forceinline__ float tanh_f(float x) { float e = __expf(2.f * x); return __fdividef(e - 1.f, e + 1.f); }

__global__ void __launch_bounds__(256, 1) recl_k(
    const float* __restrict__ Gx, const float* __restrict__ Whh,
    const float* __restrict__ hinit, int hbcast,
    const float* __restrict__ cinit, int cbcast,
    float* __restrict__ Xout, float* __restrict__ hfin, float* __restrict__ cfin)
{
    extern __shared__ __align__(16) float sm[];
    int tid  = threadIdx.x;
    int rank = blockIdx.x & 7;         // == %cluster_ctarank (1D cluster of 8)
    int grp  = blockIdx.x >> 3;
    int row  = tid & 127, kh = tid >> 7;
    int q = row >> 5, wcol = row & 31;

    // ---- load W slice [128 rows x 256] into smem (stride 260) ----
#pragma unroll
    for (int v = 0; v < 32; v++) {
        int id = tid + 256 * v;            // 8192 float4
        int lr = id >> 6, k4 = id & 63;
        int grow = (lr >> 5) * 256 + 32 * rank + (lr & 31);
        *(float4*)(sm + SM_W + lr * RW + 4 * k4) =
            __ldg((const float4*)(Whh + (size_t)grow * 256 + 4 * k4));
    }
    // ---- h0 into buffer 0 (full 4x256 copy per CTA) ----
    {
        int b = tid >> 6, k4 = tid & 63;
        float4 h4 = hbcast ? __ldg((const float4*)(hinit + 4 * k4))
                           : __ldg((const float4*)(hinit + (size_t)(4 * grp + b) * 256 + 4 * k4));
        *(float4*)(sm + SM_H0 + b * RW + 4 * k4) = h4;
    }

    int ab = tid >> 5, acol = tid & 31;         // activation mapping (tid<128)
    int b_glob = 4 * grp + ab;
    int col_glob = 32 * rank + acol;
    float creg = 0.f, hlast = 0.f;
    if (tid < 128)
        creg = cbcast ? cinit[col_glob] : cinit[(size_t)b_glob * 256 + col_glob];

    // peer smem base addresses (all 8 ranks, incl. self)
    uint32_t peer[8];
    {
        uint32_t sb = smem_u32(sm);
#pragma unroll
        for (int p = 0; p < 8; p++) {
            uint32_t pa;
            asm("mapa.shared::cluster.u32 %0, %1, %2;" : "=r"(pa) : "r"(sb), "r"(p));
            peer[p] = pa;
        }
    }
    __syncthreads();

    for (int t = 0; t < T_STEPS; t++) {
        const float* hc = sm + ((t & 1) ? SM_H1 : SM_H0);
        uint32_t hnOff  = (t & 1) ? SM_H0 : SM_H1;

        // Gx prefetch (in flight during compute)
        float gx0 = 0.f, gx1 = 0.f, gx2 = 0.f, gx3 = 0.f;
        if (tid < 128) {
            const float* gp = Gx + (size_t)(t * 64 + b_glob) * 1024 + col_glob;
            gx0 = __ldcg(gp);       gx1 = __ldcg(gp + 256);
            gx2 = __ldcg(gp + 512); gx3 = __ldcg(gp + 768);
        }

        // ---- gates: thread (row, kh) does 4 batches x 128 k ----
        const float4* wr = (const float4*)(sm + SM_W + row * RW) + kh * 32;
        const float* hb = hc + kh * 128;
        float s0 = 0.f, s1 = 0.f, s2 = 0.f, s3 = 0.f;
#pragma unroll 8
        for (int k4 = 0; k4 < 32; k4++) {
            float4 w  = wr[k4];
            float4 h0 = *(const float4*)(hb + 0 * RW + 4 * k4);
            float4 h1 = *(const float4*)(hb + 1 * RW + 4 * k4);
            float4 h2 = *(const float4*)(hb + 2 * RW + 4 * k4);
            float4 h3 = *(const float4*)(hb + 3 * RW + 4 * k4);
            s0 += w.x * h0.x + w.y * h0.y + w.z * h0.z + w.w * h0.w;
            s1 += w.x * h1.x + w.y * h1.y + w.z * h1.z + w.w * h1.w;
            s2 += w.x * h2.x + w.y * h2.y + w.z * h2.z + w.w * h2.w;
            s3 += w.x * h3.x + w.y * h3.y + w.z * h3.z + w.w * h3.w;
        }
        if (kh == 1)
            *(float4*)(sm + SM_RED + row * 4) = make_float4(s0, s1, s2, s3);
        __syncthreads();
        if (kh == 0) {
            float4 o = *(const float4*)(sm + SM_RED + row * 4);
            sm[SM_GB + q * 128 + 0 * 32 + wcol] = s0 + o.x;
            sm[SM_GB + q * 128 + 1 * 32 + wcol] = s1 + o.y;
            sm[SM_GB + q * 128 + 2 * 32 + wcol] = s2 + o.z;
            sm[SM_GB + q * 128 + 3 * 32 + wcol] = s3 + o.w;
        }
        __syncthreads();

        // ---- activation + DSMEM broadcast of owned h chunk ----
        if (tid < 128) {
            float iv = sm[SM_GB + 0 * 128 + ab * 32 + acol] + gx0;
            float fv = sm[SM_GB + 1 * 128 + ab * 32 + acol] + gx1;
            float gv = sm[SM_GB + 2 * 128 + ab * 32 + acol] + gx2;
            float ov = sm[SM_GB + 3 * 128 + ab * 32 + acol] + gx3;
            float cn = sigf(fv) * creg + sigf(iv) * tanh_f(gv);
            float hn = sigf(ov) * tanh_f(cn);
            creg = cn; hlast = hn;
            Xout[(size_t)(t * 64 + b_glob) * 256 + col_glob] = hn;
            uint32_t off = (hnOff + (uint32_t)ab * RW + (uint32_t)col_glob) * 4u;
#pragma unroll
            for (int p = 0; p < 8; p++)
                asm volatile("st.shared::cluster.f32 [%0], %1;"
                             :: "r"(peer[p] + off), "f"(hn) : "memory");
        }

        asm volatile("barrier.cluster.arrive.aligned;" ::: "memory");
        asm volatile("barrier.cluster.wait.aligned;" ::: "memory");
    }

    if (tid < 128) {
        cfin[(size_t)b_glob * 256 + col_glob] = creg;
        hfin[(size_t)b_glob * 256 + col_glob] = hlast;
    }
}

// ---------------- row argmax over V ------------------------------------------
__global__ void argmax_k(const float* __restrict__ logits, float* __restrict__ outIdx)
{
    int m = blockIdx.x;
    const float* row = logits + (size_t)m * V_SZ;
    int tid = threadIdx.x;
    float bv = -__int_as_float(0x7f800000);
    int bi = 0;
    for (int n = tid; n < V_SZ; n += 256) {
        float v = row[n];
        if (v > bv) { bv = v; bi = n; }
    }
    __shared__ float sv[256];
    __shared__ int   si[256];
    sv[tid] = bv; si[tid] = bi;
    __syncthreads();
    for (int s = 128; s > 0; s >>= 1) {
        if (tid < s) {
            float ov = sv[tid + s]; int oi = si[tid + s];
            if (ov > sv[tid] || (ov == sv[tid] && oi < si[tid])) { sv[tid] = ov; si[tid] = oi; }
        }
        __syncthreads();
    }
    if (tid == 0) outIdx[m] = (float)si[0];
}

// ---------------- cluster launch helper ---------------------------------------
static void launch_recl(const float* gx, const float* whh,
                        const float* hinit, int hbcast,
                        const float* cinit, int cbcast,
                        float* xout, float* hfin, float* cfin)
{
    cudaLaunchConfig_t cfg = {};
    cfg.gridDim = {128, 1, 1};
    cfg.blockDim = {256, 1, 1};
    cfg.dynamicSmemBytes = REC_SMEM_BYTES;
    cfg.stream = 0;
    cudaLaunchAttribute at[1];
    at[0].id = cudaLaunchAttributeClusterDimension;
    at[0].val.clusterDim = {8, 1, 1};
    cfg.attrs = at;
    cfg.numAttrs = 1;
    cudaLaunchKernelEx(&cfg, recl_k, gx, whh, hinit, hbcast, cinit, cbcast,
                       xout, hfin, cfin);
}

// ---------------- launch ------------------------------------------------------
extern "C" void kernel_launch(void* const* d_in, const int* in_sizes, int n_in,
                              void* d_out, int out_size)
{
    const int* inputs  = (const int*)d_in[0];
    const int* targets = (const int*)d_in[1];
    const float* enc_emb = (const float*)d_in[2];
    const float* enc_Wih = (const float*)d_in[3];
    const float* enc_Whh = (const float*)d_in[4];
    const float* enc_bih = (const float*)d_in[5];
    const float* enc_bhh = (const float*)d_in[6];
    const float* hidden0 = (const float*)d_in[7];
    const float* cell0   = (const float*)d_in[8];
    const float* dec_emb = (const float*)d_in[9];
    const float* dec_Wih = (const float*)d_in[10];
    const float* dec_Whh = (const float*)d_in[11];
    const float* dec_bih = (const float*)d_in[12];
    const float* dec_bhh = (const float*)d_in[13];
    const float* fc_W    = (const float*)d_in[14];
    const float* fc_b    = (const float*)d_in[15];
    float* out = (float*)d_out;

    float *bufA, *bufB, *gx, *hfin, *cfin;
    cudaGetSymbolAddress((void**)&bufA, g_bufA);
    cudaGetSymbolAddress((void**)&bufB, g_bufB);
    cudaGetSymbolAddress((void**)&gx,   g_gx);
    cudaGetSymbolAddress((void**)&hfin, g_hfin);
    cudaGetSymbolAddress((void**)&cfin, g_cfin);

    cudaFuncSetAttribute(recl_k, cudaFuncAttributeMaxDynamicSharedMemorySize, REC_SMEM_BYTES);
    cudaFuncSetAttribute(bgemm,  cudaFuncAttributeMaxDynamicSharedMemorySize, BG_SMEM);

    float* cur = bufA;
    float* nxt = bufB;

    // ---- encoder ----
    embed_k<<<M_TOT, 256>>>(inputs, enc_emb, cur, 0);
    for (int l = 0; l < 3; l++) {
        bgemm<<<148, 256, BG_SMEM>>>(cur, enc_Wih + (size_t)l * G_SZ * H_SZ,
                                     enc_bih + l * G_SZ, enc_bhh + l * G_SZ,
                                     gx, G_SZ);
        launch_recl(gx, enc_Whh + (size_t)l * G_SZ * H_SZ,
                    hidden0 + l * H_SZ, 1, cell0 + l * H_SZ, 1,
                    nxt, hfin + (size_t)l * B_SZ * H_SZ,
                    cfin + (size_t)l * B_SZ * H_SZ);
        float* tmp = cur; cur = nxt; nxt = tmp;
    }

    // ---- decoder (teacher forcing, shifted targets) ----
    embed_k<<<M_TOT, 256>>>(targets, dec_emb, cur, 1);
    for (int l = 0; l < 3; l++) {
        bgemm<<<148, 256, BG_SMEM>>>(cur, dec_Wih + (size_t)l * G_SZ * H_SZ,
                                     dec_bih + l * G_SZ, dec_bhh + l * G_SZ,
                                     gx, G_SZ);
        launch_recl(gx, dec_Whh + (size_t)l * G_SZ * H_SZ,
                    hfin + (size_t)l * B_SZ * H_SZ, 0,
                    cfin + (size_t)l * B_SZ * H_SZ, 0,
                    nxt, hfin + (size_t)l * B_SZ * H_SZ,
                    cfin + (size_t)l * B_SZ * H_SZ);
        float* tmp = cur; cur = nxt; nxt = tmp;
    }

    // ---- FC projection to vocab (bf16 2-split mma.sync) ----
    bgemm<<<148, 256, BG_SMEM>>>(cur, fc_W, fc_b, (const float*)nullptr, out, V_SZ);

    // ---- predicted words ----
    long long need = (long long)M_TOT * V_SZ + M_TOT;
    if ((long long)out_size >= need)
        argmax_k<<<M_TOT, 256>>>(out, out + (size_t)M_TOT * V_SZ);
}